// round 17
// baseline (speedup 1.0000x reference)
#include <cuda_runtime.h>
#include <cuda_bf16.h>
#include <math.h>

// Problem constants
#define BATCH 4
#define NN 4096
#define DD 256
#define PP 64
#define ALPHA 0.2f
#define KCAP 255

#define NMAIN      (BATCH * 256)          // 1024 main blocks (16 rows each)
#define MAIN_BASE  BATCH                  // 4
#define MLP_BASE   (MAIN_BASE + NMAIN)    // 1028
#define FIN_BASE   (MLP_BASE + BATCH * 8) // 1060
#define GRID_SZ    (FIN_BASE + BATCH)     // 1064

// Scratch + handshake flags (no cudaMalloc; zero-init at load, flags reset
// by finalize each run for graph-replay determinism)
__device__ float g_v[BATCH][DD];
__device__ float g_hp[BATCH][8][128];
__device__ int   g_clist[BATCH][NN];      // ordered cluster indices
__device__ int   g_clen[BATCH];
__device__ unsigned long long g_keys[BATCH][NN];
__device__ int   g_flag_v[BATCH];
__device__ int   g_done[BATCH];
__device__ int   g_mlp_done[BATCH];

struct SmemSetup {
    alignas(16) float x[DD];
    alignas(16) float q[PP];
    alignas(16) float qpart[4][PP];
    int seed;
};
struct SmemMain {
    alignas(16) float v[DD];              // only v — no cm tile anymore
};
struct SmemMlp {
    alignas(16) float hp[2][128];
};
struct SmemFin {
    float h[128];
    float part[8];
    float theta;
    int   hist[256];
    int   wsum[8];
    int   cnt;
    unsigned long long prefix;
    int   k;
};
union SmemU {
    SmemSetup s;
    SmemMain  m;
    SmemMlp   p;
    SmemFin   f;
};

__global__ void __launch_bounds__(256) fused_kernel(
        const float* __restrict__ x,
        const float* __restrict__ adj,
        const float* __restrict__ cmask,
        const float* __restrict__ candmask,
        const float* __restrict__ seed_ctx,
        const float* __restrict__ local_stats,
        const float* __restrict__ Wq,
        const float* __restrict__ Wk,
        const float* __restrict__ w1,
        const float* __restrict__ b1,
        const float* __restrict__ w2,
        const float* __restrict__ b2,
        float* __restrict__ out)
{
    __shared__ __align__(16) SmemU su;
    const int bid = blockIdx.x;
    const int t   = threadIdx.x;

    // =====================================================================
    // Role 1: setup — seed -> q -> v, cluster index list, then flag
    // =====================================================================
    if (bid < MAIN_BASE) {
        const int b    = bid;
        const int lane = t & 31;
        if (t == 0) su.s.seed = NN;
        __syncthreads();

        {   // first index with cmask > 0.5
            int lm = NN;
            #pragma unroll
            for (int j = 15; j >= 0; j--) {
                int i = j * 256 + t;
                if (cmask[(size_t)b * NN + i] > 0.5f) lm = i;
            }
            #pragma unroll
            for (int o = 16; o > 0; o >>= 1)
                lm = min(lm, __shfl_xor_sync(0xffffffffu, lm, o));
            if (lane == 0 && lm < NN) atomicMin(&su.s.seed, lm);
        }
        __syncthreads();
        const int seed = (su.s.seed < NN) ? su.s.seed : 0;

        su.s.x[t] = x[((size_t)b * NN + seed) * DD + t];
        __syncthreads();

        {   // q[p] = sum_d x_seed[d] * Wq[d,p] : 4 chunks x 64 p, 64 each
            const int p = t & 63;
            const int c = t >> 6;
            float acc = 0.f;
            #pragma unroll 8
            for (int dd = 0; dd < 64; dd++) {
                int d = c * 64 + dd;
                acc += su.s.x[d] * Wq[d * PP + p];
            }
            su.s.qpart[c][p] = acc;
        }
        __syncthreads();
        if (t < PP)
            su.s.q[t] = (su.s.qpart[0][t] + su.s.qpart[1][t])
                      + (su.s.qpart[2][t] + su.s.qpart[3][t]);
        __syncthreads();

        {   // v[d] = (Wk[d,:] . q) / 8 : one thread per d
            const int d = t;
            const float4* wk4 = (const float4*)(Wk + d * PP);
            const float4* q4  = (const float4*)su.s.q;
            float a = 0.f;
            #pragma unroll
            for (int k = 0; k < 16; k++) {
                float4 wv = wk4[k];
                float4 qv = q4[k];
                a += wv.x * qv.x + wv.y * qv.y + wv.z * qv.z + wv.w * qv.w;
            }
            g_v[b][d] = a * 0.125f;
        }
        __syncthreads();

        // ordered cluster-index list (warp 0): ballot compaction, ascending
        if (t < 32) {
            int cnt = 0;
            for (int base = 0; base < NN; base += 32) {
                float cv = cmask[(size_t)b * NN + base + t];
                unsigned m = __ballot_sync(0xffffffffu, cv > 0.5f);
                if (cv > 0.5f) {
                    int pos = cnt + __popc(m & ((1u << t) - 1u));
                    g_clist[b][pos] = base + t;
                }
                cnt += __popc(m);
            }
            if (t == 0) g_clen[b] = cnt;
        }
        __syncthreads();
        if (t == 0) { __threadfence(); atomicExch(&g_flag_v[b], 1); }
        return;
    }

    // =====================================================================
    // Role 3: theta-MLP partial blocks
    // =====================================================================
    if (bid >= MLP_BASE && bid < FIN_BASE) {
        const int m     = bid - MLP_BASE;
        const int b     = m >> 3;
        const int chunk = m & 7;
        const int h     = t & 127;
        const int half  = t >> 7;            // 0/1, 32 inputs each
        float a = 0.f;
        #pragma unroll
        for (int ii = 0; ii < 32; ii++) {
            int g = chunk * 64 + half * 32 + ii;
            float inv = (g < 384) ? seed_ctx[(size_t)b * 384 + g]
                                  : local_stats[(size_t)b * 128 + (g - 384)];
            a += inv * w1[g * 128 + h];
        }
        su.p.hp[half][h] = a;
        __syncthreads();
        if (t < 128)
            g_hp[b][chunk][t] = su.p.hp[0][t] + su.p.hp[1][t];
        __syncthreads();
        if (t == 0) { __threadfence(); atomicAdd(&g_mlp_done[b], 1); }
        return;
    }

    // =====================================================================
    // Role 2: main streaming — deg-only dense scan (8 LDG.128 in flight),
    // sparse e2c from cluster list, x.v late. 2 rows per warp.
    // =====================================================================
    if (bid < MLP_BASE) {
        const int m    = bid - MAIN_BASE;
        const int b    = m >> 8;
        const int blk  = m & 255;
        const int w    = t >> 5;             // 0..7
        const int lane = t & 31;
        const int n0   = (blk << 4) + (w << 1);
        const int n1   = n0 + 1;
        float* out_score = out + BATCH * NN;

        const float4* a0 = (const float4*)(adj + ((size_t)b * NN + n0) * NN);
        const float4* a1 = (const float4*)(adj + ((size_t)b * NN + n1) * NN);

        float d0 = 0.f, d1 = 0.f;
        #pragma unroll 1
        for (int i = lane; i < NN / 4; i += 128) {
            float4 A0 = a0[i], B0 = a0[i + 32], C0 = a0[i + 64], D0 = a0[i + 96];
            float4 A1 = a1[i], B1 = a1[i + 32], C1 = a1[i + 64], D1 = a1[i + 96];
            d0 += (((A0.x + A0.y) + (A0.z + A0.w)) + ((B0.x + B0.y) + (B0.z + B0.w)))
                + (((C0.x + C0.y) + (C0.z + C0.w)) + ((D0.x + D0.y) + (D0.z + D0.w)));
            d1 += (((A1.x + A1.y) + (A1.z + A1.w)) + ((B1.x + B1.y) + (B1.z + B1.w)))
                + (((C1.x + C1.y) + (C1.z + C1.w)) + ((D1.x + D1.y) + (D1.z + D1.w)));
        }

        // ---- acquire setup results (flag long set by now) ----
        if (t == 0) { while (atomicAdd(&g_flag_v[b], 0) == 0) { } }
        __syncthreads();
        __threadfence();
        su.m.v[t] = __ldcg(&g_v[b][t]);
        __syncthreads();

        // sparse e2c: sums of exact 0/1 floats -> order-independent exact
        float e0 = 0.f, e1 = 0.f;
        {
            const int len = __ldcg(&g_clen[b]);
            const float* r0 = adj + ((size_t)b * NN + n0) * NN;
            const float* r1 = adj + ((size_t)b * NN + n1) * NN;
            for (int j = lane; j < len; j += 32) {
                int idx = __ldcg(&g_clist[b][j]);
                e0 += r0[idx];
                e1 += r1[idx];
            }
        }

        float sc0 = 0.f, sc1 = 0.f;
        {
            const float4* x0 = (const float4*)(x + ((size_t)b * NN + n0) * DD);
            const float4* x1 = (const float4*)(x + ((size_t)b * NN + n1) * DD);
            const float4* v4 = (const float4*)su.m.v;
            #pragma unroll
            for (int i = lane; i < DD / 4; i += 32) {
                float4 xv0 = x0[i], xv1 = x1[i], vv = v4[i];
                sc0 += xv0.x * vv.x + xv0.y * vv.y + xv0.z * vv.z + xv0.w * vv.w;
                sc1 += xv1.x * vv.x + xv1.y * vv.y + xv1.z * vv.z + xv1.w * vv.w;
            }
        }

        #pragma unroll
        for (int o = 16; o > 0; o >>= 1) {
            d0  += __shfl_xor_sync(0xffffffffu, d0,  o);
            d1  += __shfl_xor_sync(0xffffffffu, d1,  o);
            e0  += __shfl_xor_sync(0xffffffffu, e0,  o);
            e1  += __shfl_xor_sync(0xffffffffu, e1,  o);
            sc0 += __shfl_xor_sync(0xffffffffu, sc0, o);
            sc1 += __shfl_xor_sync(0xffffffffu, sc1, o);
        }

        if (lane == 0) {
            float dd0 = fmaxf(d0, 1.0f), dd1 = fmaxf(d1, 1.0f);
            out_score[(size_t)b * NN + n0] = sc0 + ALPHA * (e0 / dd0);
            out_score[(size_t)b * NN + n1] = sc1 + ALPHA * (e1 / dd1);
        }
        __syncthreads();
        if (t == 0) { __threadfence(); atomicAdd(&g_done[b], 1); }
        return;
    }

    // =====================================================================
    // Role 4: finalize (keys in global; smem stays tiny)
    // =====================================================================
    {
        const int b = bid - FIN_BASE;
        float* out_hard = out;
        float* out_p    = out + BATCH * NN;   // raw scores on entry

        if (t == 0) {
            while (atomicAdd(&g_done[b], 0) < 256)   __nanosleep(128);
            while (atomicAdd(&g_mlp_done[b], 0) < 8) __nanosleep(64);
        }
        __syncthreads();
        __threadfence();

        if (t == 0) { su.f.cnt = 0; su.f.prefix = 0ULL; su.f.k = KCAP; }

        // theta = relu(sum partials + b1) . w2 + b2
        if (t < 128) {
            float a = b1[t];
            #pragma unroll
            for (int c = 0; c < 8; c++) a += __ldcg(&g_hp[b][c][t]);
            su.f.h[t] = fmaxf(a, 0.f) * w2[t];
        }
        __syncthreads();
        if (t < 32) {
            float a = su.f.h[t] + su.f.h[t + 32] + su.f.h[t + 64] + su.f.h[t + 96];
            #pragma unroll
            for (int o = 16; o > 0; o >>= 1) a += __shfl_xor_sync(0xffffffffu, a, o);
            if (t == 0) su.f.theta = a + b2[0];
        }
        __syncthreads();
        const float theta = su.f.theta;

        // p, keys -> global, count(p>0.5) — 16 elements per thread
        int cnt = 0;
        #pragma unroll
        for (int j = 0; j < 16; j++) {
            int i = j * 256 + t;
            float sc = __ldcg(&out_p[(size_t)b * NN + i]);
            float p = 1.0f / (1.0f + expf(-(sc - theta)));
            p *= candmask[(size_t)b * NN + i];
            g_keys[b][i] = ((unsigned long long)__float_as_uint(p) << 32)
                         | (unsigned int)(~i);
            cnt += (p > 0.5f) ? 1 : 0;
        }
        #pragma unroll
        for (int o = 16; o > 0; o >>= 1) cnt += __shfl_xor_sync(0xffffffffu, cnt, o);
        if ((t & 31) == 0) atomicAdd(&su.f.cnt, cnt);
        __syncthreads();

        const bool trim = (su.f.cnt > KCAP);
        if (trim) {
            for (int round = 0; round < 8; round++) {
                const int shift = 56 - 8 * round;
                const int kreg = su.f.k;
                const unsigned long long prefix = su.f.prefix;
                su.f.hist[t] = 0;                 // t<256 == exactly 256 bins
                __syncthreads();
                const int hshift = shift + 8;
                #pragma unroll
                for (int j = 0; j < 16; j++) {
                    unsigned long long key = g_keys[b][j * 256 + t];
                    bool match = (round == 0) ||
                                 ((key >> hshift) == (prefix >> hshift));
                    if (match) atomicAdd(&su.f.hist[(int)((key >> shift) & 255ULL)], 1);
                }
                __syncthreads();
                // parallel suffix-scan over 256 bins, pick unique winner
                int h = su.f.hist[t];
                int Sloc = h;
                const int l = t & 31;
                #pragma unroll
                for (int o = 1; o < 32; o <<= 1) {
                    int v = __shfl_down_sync(0xffffffffu, Sloc, o);
                    if (l + o < 32) Sloc += v;
                }
                if (l == 0) su.f.wsum[t >> 5] = Sloc;
                __syncthreads();
                {
                    int S = Sloc;
                    for (int wi = (t >> 5) + 1; wi < 8; wi++) S += su.f.wsum[wi];
                    if (S >= kreg && (S - h) < kreg) {
                        su.f.k = kreg - (S - h);
                        su.f.prefix = prefix | ((unsigned long long)t << shift);
                    }
                }
                __syncthreads();
            }
        }
        const unsigned long long kth = trim ? su.f.prefix : 0ULL;

        // write outputs + trimmed sum (deterministic tree reduce)
        float lsum = 0.f;
        #pragma unroll
        for (int j = 0; j < 16; j++) {
            int i = j * 256 + t;
            unsigned long long key = g_keys[b][i];
            float p = __uint_as_float((unsigned int)(key >> 32));
            if (key < kth) p = 0.f;
            out_p[(size_t)b * NN + i]    = p;
            out_hard[(size_t)b * NN + i] = (p > 0.5f) ? 1.0f : 0.0f;
            lsum += p;
        }
        #pragma unroll
        for (int o = 16; o > 0; o >>= 1) lsum += __shfl_xor_sync(0xffffffffu, lsum, o);
        if ((t & 31) == 0) su.f.part[t >> 5] = lsum;
        __syncthreads();
        if (t < 32) {
            float a = (t < 8) ? su.f.part[t] : 0.f;
            #pragma unroll
            for (int o = 16; o > 0; o >>= 1) a += __shfl_xor_sync(0xffffffffu, a, o);
            if (t == 0) {
                float* tail = out + 2 * BATCH * NN;
                tail[b]             = theta;
                tail[BATCH + b]     = a;
                tail[2 * BATCH + b] = a * (1.0f / (float)NN);
            }
        }
        __syncthreads();
        if (t == 0) {
            atomicExch(&g_flag_v[b], 0);
            atomicExch(&g_done[b], 0);
            atomicExch(&g_mlp_done[b], 0);
        }
    }
}

// ---------------------------------------------------------------------------
extern "C" void kernel_launch(void* const* d_in, const int* in_sizes, int n_in,
                              void* d_out, int out_size)
{
    const float* x           = (const float*)d_in[0];
    const float* adj         = (const float*)d_in[1];
    const float* seed_ctx    = (const float*)d_in[2];
    const float* local_stats = (const float*)d_in[3];
    const float* cmask       = (const float*)d_in[4];
    const float* candmask    = (const float*)d_in[5];
    const float* Wq          = (const float*)d_in[6];
    const float* Wk          = (const float*)d_in[7];
    const float* w1          = (const float*)d_in[8];
    const float* b1          = (const float*)d_in[9];
    const float* w2          = (const float*)d_in[10];
    const float* b2          = (const float*)d_in[11];
    float* out = (float*)d_out;

    fused_kernel<<<GRID_SZ, 256>>>(x, adj, cmask, candmask, seed_ctx,
                                   local_stats, Wq, Wk, w1, b1, w2, b2, out);
}